// round 16
// baseline (speedup 1.0000x reference)
#include <cuda_runtime.h>

// Holt double-exponential smoothing, ALPHA = BETA = 0.5.
// x: [B=32, N=2048, T=1024] f32, T contiguous.
//
// Linear recurrence: state=(s,b), state' = M*state + c*x with
//   M = [[0.5,0.5],[-0.25,0.75]], c = (0.5, 0.25).
// Quirky init (out[0]=0, out[1]=x1, scan from t=2 with (0,0)) == zero
// x[0],x[1], run the uniform recurrence from (0,0), patch out[1]=x1.
//
// FINAL champion (terminal): one WARP per sequence, lanes hold
// consecutive float4 groups -> fully coalesced 512B transactions.
// Kogge-Stone scan over affine offsets with constexpr matrix powers,
// decay-truncated to 3 steps (|eig(M)|=0.707 -> M^32/M^64 terms
// < 1.5e-5, below the 1e-3 tolerance). Streaming loads/stores; all 8
// tile loads front-batched (MLP=8 — required; batch-4 lost 160 GB/s).
//
// Session evidence (6 runs, 81.95-82.69 us): ~6.36-6.39 TB/s is the
// hard HBM R/W-turnaround ceiling for this 50/50 stream (80% of spec),
// invariant across occ 49-85% and five kernel structures. Best ncu
// kernel time 75.4 us == the 75.5 us floor at that bandwidth (~100%
// of achievable). Closed probes: forcing 32 regs spills (+15 us);
// MLP 8->4 drops BW 2.5%; R/W interleave hurts; issue trims neutral;
// stores are fully-covered (no read-for-ownership) so traffic is the
// compulsory 512 MB minimum.

static constexpr int STEPS = 1024;
static constexpr int VEC4  = STEPS / 4;   // 256 float4 per sequence
static constexpr int NSEQ  = 32 * 2048;   // 65536 sequences = 65536 warps
static constexpr int TPB   = 256;         // 8 warps/block
static constexpr int WPB   = TPB / 32;
static constexpr int ITERS = VEC4 / 32;   // 8 iterations of 128 timesteps

// ---- compile-time 2x2 matrix powers (exact dyadic rationals in double) ----
struct M22 { double a, b, c, d; };
constexpr M22 mmul(M22 p, M22 q) {
    return { p.a*q.a + p.b*q.c, p.a*q.b + p.b*q.d,
             p.c*q.a + p.d*q.c, p.c*q.b + p.d*q.d };
}
constexpr M22 Mm1  {0.5, 0.5, -0.25, 0.75};
constexpr M22 Mm2  = mmul(Mm1,  Mm1);
constexpr M22 Mm4  = mmul(Mm2,  Mm2);
constexpr M22 Mm8  = mmul(Mm4,  Mm4);
constexpr M22 Mm16 = mmul(Mm8,  Mm8);

// M^k * c coefficients for the local 4-step fold:
//   state_out = M^4*state_in + M^3c*x0 + M^2c*x1 + Mc*x2 + c*x3
#define C_S    0.5f
#define C_B    0.25f
#define M1C_S  0.375f
#define M1C_B  0.0625f
#define M2C_S  0.21875f
#define M2C_B  (-0.046875f)
#define M3C_S  0.0859375f
#define M3C_B  (-0.08984375f)

__device__ __forceinline__ float holt_step(float& s, float& b, float xv) {
    float sn = fmaf(0.5f, s + b, 0.5f * xv);
    b = fmaf(0.5f, sn - s, 0.5f * b);
    s = sn;
    return sn;
}

// one Kogge-Stone scan step with constant matrix P = M^(4k)
#define SCAN_STEP(K, P)                                                     \
    {                                                                       \
        float ps = __shfl_up_sync(0xFFFFFFFFu, es, (K));                    \
        float pb = __shfl_up_sync(0xFFFFFFFFu, eb, (K));                    \
        if (lane >= (K)) {                                                  \
            es = fmaf((float)(P).a, ps, fmaf((float)(P).b, pb, es));        \
            eb = fmaf((float)(P).c, ps, fmaf((float)(P).d, pb, eb));        \
        }                                                                   \
    }

__global__ __launch_bounds__(TPB)
void holt_scan_kernel(const float* __restrict__ x, float* __restrict__ y) {
    const int lane = threadIdx.x & 31;
    const int seq  = blockIdx.x * WPB + (threadIdx.x >> 5);

    const float4* __restrict__ xin  = reinterpret_cast<const float4*>(x) + (size_t)seq * VEC4;
    float4*       __restrict__ yout = reinterpret_cast<float4*>(y)       + (size_t)seq * VEC4;

    // Front-batch all 8 tile loads: independent addresses -> MLP=8.
    // Streaming (.cs): every line is read exactly once chip-wide.
    float4 v[ITERS];
    #pragma unroll
    for (int it = 0; it < ITERS; ++it)
        v[it] = __ldcs(&xin[it * 32 + lane]);          // coalesced 512B warp loads

    float cs = 0.0f, cb = 0.0f;   // carry state across 128-step iterations

    #pragma unroll
    for (int it = 0; it < ITERS; ++it) {
        float4 w = v[it];

        float patch = w.y;                             // original x[1] (lane0/it0)
        if (it == 0 && lane == 0) { w.x = 0.0f; w.y = 0.0f; }

        // local affine offset for this lane's 4 steps
        float es = fmaf(M3C_S, w.x, fmaf(M2C_S, w.y, fmaf(M1C_S, w.z, C_S * w.w)));
        float eb = fmaf(M3C_B, w.x, fmaf(M2C_B, w.y, fmaf(M1C_B, w.z, C_B * w.w)));

        // fold iteration carry into lane 0: e0 = M^4 * carry + d0
        if (lane == 0) {
            es = fmaf((float)Mm4.a, cs, fmaf((float)Mm4.b, cb, es));
            eb = fmaf((float)Mm4.c, cs, fmaf((float)Mm4.d, cb, eb));
        }

        // truncated inclusive scan: steps K=8 (M^32, ~1.5e-5) and K=16
        // (M^64, ~2e-10) dropped — below fp32 noise vs 1e-3 tolerance.
        SCAN_STEP(1, Mm4)
        SCAN_STEP(2, Mm8)
        SCAN_STEP(4, Mm16)

        // exclusive prefix = state at the START of this lane's 4 steps
        float ss = __shfl_up_sync(0xFFFFFFFFu, es, 1);
        float sb = __shfl_up_sync(0xFFFFFFFFu, eb, 1);
        if (lane == 0) { ss = cs; sb = cb; }

        // next carry = lane 31's inclusive state
        cs = __shfl_sync(0xFFFFFFFFu, es, 31);
        cb = __shfl_sync(0xFFFFFFFFu, eb, 31);

        // serial replay of the 4 steps to produce outputs
        float4 o;
        o.x = holt_step(ss, sb, w.x);
        o.y = holt_step(ss, sb, w.y);
        o.z = holt_step(ss, sb, w.z);
        o.w = holt_step(ss, sb, w.w);

        if (it == 0 && lane == 0) { o.x = 0.0f; o.y = patch; }  // t=0, t=1 quirks

        __stcs(&yout[it * 32 + lane], o);              // coalesced streaming store
    }
}

extern "C" void kernel_launch(void* const* d_in, const int* in_sizes, int n_in,
                              void* d_out, int out_size) {
    (void)in_sizes; (void)n_in; (void)out_size;
    const float* x = (const float*)d_in[0];
    float*       y = (float*)d_out;
    holt_scan_kernel<<<NSEQ / WPB, TPB>>>(x, y);
}

// round 17
// speedup vs baseline: 1.0023x; 1.0023x over previous
#include <cuda_runtime.h>

// Holt double-exponential smoothing, ALPHA = BETA = 0.5.
// x: [B=32, N=2048, T=1024] f32, T contiguous.
//
// Linear recurrence: state=(s,b), state' = M*state + c*x with
//   M = [[0.5,0.5],[-0.25,0.75]], c = (0.5, 0.25).
// Quirky init (out[0]=0, out[1]=x1, scan from t=2 with (0,0)) == zero
// x[0],x[1], run the uniform recurrence from (0,0), patch out[1]=x1.
//
// FINAL champion (session closed): one WARP per sequence, lanes hold
// consecutive float4 groups -> fully coalesced 512B transactions.
// Kogge-Stone scan over affine offsets with constexpr matrix powers,
// decay-truncated to 3 steps (|eig(M)|=0.707 -> M^32/M^64 terms
// < 1.5e-5, below the 1e-3 tolerance). Streaming loads/stores; all 8
// tile loads front-batched (MLP=8 — required; batch-4 lost 160 GB/s).
//
// Session: 193.4 -> 81.95 us (2.36x). Seven timed runs 81.95-82.69 us.
// ncu kernel time 75.4-76.0 us vs 75.5 us floor (512 MB compulsory
// traffic at the measured 6.36-6.39 TB/s HBM R/W-turnaround ceiling,
// 80% of spec) -> 99-100% of achievable. Ceiling shown invariant
// across five kernel structures, occ 49-85%, MLP 4-8, two cache
// policies. Closed probes: forcing 32 regs spills (+15 us); MLP 8->4
// drops BW 2.5%; R/W interleave hurts; issue-side trims neutral.

static constexpr int STEPS = 1024;
static constexpr int VEC4  = STEPS / 4;   // 256 float4 per sequence
static constexpr int NSEQ  = 32 * 2048;   // 65536 sequences = 65536 warps
static constexpr int TPB   = 256;         // 8 warps/block
static constexpr int WPB   = TPB / 32;
static constexpr int ITERS = VEC4 / 32;   // 8 iterations of 128 timesteps

// ---- compile-time 2x2 matrix powers (exact dyadic rationals in double) ----
struct M22 { double a, b, c, d; };
constexpr M22 mmul(M22 p, M22 q) {
    return { p.a*q.a + p.b*q.c, p.a*q.b + p.b*q.d,
             p.c*q.a + p.d*q.c, p.c*q.b + p.d*q.d };
}
constexpr M22 Mm1  {0.5, 0.5, -0.25, 0.75};
constexpr M22 Mm2  = mmul(Mm1,  Mm1);
constexpr M22 Mm4  = mmul(Mm2,  Mm2);
constexpr M22 Mm8  = mmul(Mm4,  Mm4);
constexpr M22 Mm16 = mmul(Mm8,  Mm8);

// M^k * c coefficients for the local 4-step fold:
//   state_out = M^4*state_in + M^3c*x0 + M^2c*x1 + Mc*x2 + c*x3
#define C_S    0.5f
#define C_B    0.25f
#define M1C_S  0.375f
#define M1C_B  0.0625f
#define M2C_S  0.21875f
#define M2C_B  (-0.046875f)
#define M3C_S  0.0859375f
#define M3C_B  (-0.08984375f)

__device__ __forceinline__ float holt_step(float& s, float& b, float xv) {
    float sn = fmaf(0.5f, s + b, 0.5f * xv);
    b = fmaf(0.5f, sn - s, 0.5f * b);
    s = sn;
    return sn;
}

// one Kogge-Stone scan step with constant matrix P = M^(4k)
#define SCAN_STEP(K, P)                                                     \
    {                                                                       \
        float ps = __shfl_up_sync(0xFFFFFFFFu, es, (K));                    \
        float pb = __shfl_up_sync(0xFFFFFFFFu, eb, (K));                    \
        if (lane >= (K)) {                                                  \
            es = fmaf((float)(P).a, ps, fmaf((float)(P).b, pb, es));        \
            eb = fmaf((float)(P).c, ps, fmaf((float)(P).d, pb, eb));        \
        }                                                                   \
    }

__global__ __launch_bounds__(TPB)
void holt_scan_kernel(const float* __restrict__ x, float* __restrict__ y) {
    const int lane = threadIdx.x & 31;
    const int seq  = blockIdx.x * WPB + (threadIdx.x >> 5);

    const float4* __restrict__ xin  = reinterpret_cast<const float4*>(x) + (size_t)seq * VEC4;
    float4*       __restrict__ yout = reinterpret_cast<float4*>(y)       + (size_t)seq * VEC4;

    // Front-batch all 8 tile loads: independent addresses -> MLP=8.
    // Streaming (.cs): every line is read exactly once chip-wide.
    float4 v[ITERS];
    #pragma unroll
    for (int it = 0; it < ITERS; ++it)
        v[it] = __ldcs(&xin[it * 32 + lane]);          // coalesced 512B warp loads

    float cs = 0.0f, cb = 0.0f;   // carry state across 128-step iterations

    #pragma unroll
    for (int it = 0; it < ITERS; ++it) {
        float4 w = v[it];

        float patch = w.y;                             // original x[1] (lane0/it0)
        if (it == 0 && lane == 0) { w.x = 0.0f; w.y = 0.0f; }

        // local affine offset for this lane's 4 steps
        float es = fmaf(M3C_S, w.x, fmaf(M2C_S, w.y, fmaf(M1C_S, w.z, C_S * w.w)));
        float eb = fmaf(M3C_B, w.x, fmaf(M2C_B, w.y, fmaf(M1C_B, w.z, C_B * w.w)));

        // fold iteration carry into lane 0: e0 = M^4 * carry + d0
        if (lane == 0) {
            es = fmaf((float)Mm4.a, cs, fmaf((float)Mm4.b, cb, es));
            eb = fmaf((float)Mm4.c, cs, fmaf((float)Mm4.d, cb, eb));
        }

        // truncated inclusive scan: steps K=8 (M^32, ~1.5e-5) and K=16
        // (M^64, ~2e-10) dropped — below fp32 noise vs 1e-3 tolerance.
        SCAN_STEP(1, Mm4)
        SCAN_STEP(2, Mm8)
        SCAN_STEP(4, Mm16)

        // exclusive prefix = state at the START of this lane's 4 steps
        float ss = __shfl_up_sync(0xFFFFFFFFu, es, 1);
        float sb = __shfl_up_sync(0xFFFFFFFFu, eb, 1);
        if (lane == 0) { ss = cs; sb = cb; }

        // next carry = lane 31's inclusive state
        cs = __shfl_sync(0xFFFFFFFFu, es, 31);
        cb = __shfl_sync(0xFFFFFFFFu, eb, 31);

        // serial replay of the 4 steps to produce outputs
        float4 o;
        o.x = holt_step(ss, sb, w.x);
        o.y = holt_step(ss, sb, w.y);
        o.z = holt_step(ss, sb, w.z);
        o.w = holt_step(ss, sb, w.w);

        if (it == 0 && lane == 0) { o.x = 0.0f; o.y = patch; }  // t=0, t=1 quirks

        __stcs(&yout[it * 32 + lane], o);              // coalesced streaming store
    }
}

extern "C" void kernel_launch(void* const* d_in, const int* in_sizes, int n_in,
                              void* d_out, int out_size) {
    (void)in_sizes; (void)n_in; (void)out_size;
    const float* x = (const float*)d_in[0];
    float*       y = (float*)d_out;
    holt_scan_kernel<<<NSEQ / WPB, TPB>>>(x, y);
}